// round 4
// baseline (speedup 1.0000x reference)
#include <cuda_runtime.h>
#include <math.h>

#define NN 8192
#define FF 64
#define SLOPEC 3.0f

// ---------------- scratch (device globals; no allocations allowed) -------------
__device__ float g_xe[NN * FF];                      // encoded features (2 MB)
__device__ float g_S[(size_t)NN * NN];               // logits S = xe xe^T (256 MB)
__device__ float g_dpart[32 * NN];                   // partial column sums of exp(S)
__device__ float g_invD[NN];                         // 1 / column sum
__device__ float g_outpart[8 * NN * FF];             // K-split partials of attn@xe (16 MB)
__device__ float g_colsum_part[32 * FF];
__device__ float g_sumsq_part[32];

// ---------------- K1: per-element encoder MLP 2->4->4->1 (tanh each) ----------
__global__ void k_encode(const float* __restrict__ x,
                         const float* __restrict__ w1, const float* __restrict__ b1,
                         const float* __restrict__ w2, const float* __restrict__ b2,
                         const float* __restrict__ w3, const float* __restrict__ b3) {
    int idx = blockIdx.x * 256 + threadIdx.x;        // < NN*FF
    float2 xv = ((const float2*)x)[idx];
    float h1[4], h2[4];
#pragma unroll
    for (int j = 0; j < 4; j++)
        h1[j] = tanhf(xv.x * __ldg(w1 + j) + xv.y * __ldg(w1 + 4 + j) + __ldg(b1 + j));
#pragma unroll
    for (int j = 0; j < 4; j++)
        h2[j] = tanhf(h1[0] * __ldg(w2 + j) + h1[1] * __ldg(w2 + 4 + j) +
                      h1[2] * __ldg(w2 + 8 + j) + h1[3] * __ldg(w2 + 12 + j) + __ldg(b2 + j));
    float o = tanhf(h2[0] * __ldg(w3 + 0) + h2[1] * __ldg(w3 + 1) +
                    h2[2] * __ldg(w3 + 2) + h2[3] * __ldg(w3 + 3) + __ldg(b3));
    g_xe[idx] = o;
}

// ---------------- K2: S = xe * xe^T  (fp32, 128x128 tile, K=64) ---------------
#define SPAD 132   // padded tile row length; 132*4 bytes is 16B-aligned, reduces STS conflicts
__global__ __launch_bounds__(256, 2) void k_gemm_s() {
    __shared__ float sa[32][SPAD];   // [k][m] transposed A tile (i rows)
    __shared__ float sb[32][SPAD];   // [k][n] transposed A tile (j rows)
    const int i0 = blockIdx.y * 128;
    const int j0 = blockIdx.x * 128;
    const int t  = threadIdx.x;
    const int tx = t & 15, ty = t >> 4;
    const int kf4 = t & 7, rr = t >> 3;     // load mapping: 8 f4 per k-row, 32 row groups

    float acc[2][2][4][4];
#pragma unroll
    for (int a = 0; a < 2; a++)
#pragma unroll
        for (int b = 0; b < 2; b++)
#pragma unroll
            for (int r = 0; r < 4; r++)
#pragma unroll
                for (int c = 0; c < 4; c++) acc[a][b][r][c] = 0.f;

    for (int kb = 0; kb < 64; kb += 32) {
        __syncthreads();
#pragma unroll
        for (int l = 0; l < 4; l++) {
            int row = rr + l * 32;
            float4 va = *(const float4*)(g_xe + (size_t)(i0 + row) * FF + kb + kf4 * 4);
            sa[kf4 * 4 + 0][row] = va.x; sa[kf4 * 4 + 1][row] = va.y;
            sa[kf4 * 4 + 2][row] = va.z; sa[kf4 * 4 + 3][row] = va.w;
            float4 vb = *(const float4*)(g_xe + (size_t)(j0 + row) * FF + kb + kf4 * 4);
            sb[kf4 * 4 + 0][row] = vb.x; sb[kf4 * 4 + 1][row] = vb.y;
            sb[kf4 * 4 + 2][row] = vb.z; sb[kf4 * 4 + 3][row] = vb.w;
        }
        __syncthreads();
#pragma unroll 4
        for (int k = 0; k < 32; k++) {
            float a0[4], a1[4], b0[4], b1[4];
            *(float4*)a0 = *(const float4*)&sa[k][ty * 4];
            *(float4*)a1 = *(const float4*)&sa[k][64 + ty * 4];
            *(float4*)b0 = *(const float4*)&sb[k][tx * 4];
            *(float4*)b1 = *(const float4*)&sb[k][64 + tx * 4];
#pragma unroll
            for (int r = 0; r < 4; r++)
#pragma unroll
                for (int c = 0; c < 4; c++) {
                    acc[0][0][r][c] += a0[r] * b0[c];
                    acc[0][1][r][c] += a0[r] * b1[c];
                    acc[1][0][r][c] += a1[r] * b0[c];
                    acc[1][1][r][c] += a1[r] * b1[c];
                }
        }
    }
#pragma unroll
    for (int a = 0; a < 2; a++)
#pragma unroll
        for (int r = 0; r < 4; r++) {
            size_t i = (size_t)(i0 + a * 64 + ty * 4 + r);
            float4 v0 = make_float4(acc[a][0][r][0], acc[a][0][r][1], acc[a][0][r][2], acc[a][0][r][3]);
            float4 v1 = make_float4(acc[a][1][r][0], acc[a][1][r][1], acc[a][1][r][2], acc[a][1][r][3]);
            *(float4*)(g_S + i * NN + j0 + tx * 4)      = v0;
            *(float4*)(g_S + i * NN + j0 + 64 + tx * 4) = v1;
        }
}

// ---------------- K3: partial column sums of exp(S) ---------------------------
// |S| < 64 strictly (tanh outputs), so exp(S) and its sums stay in fp32 range;
// skipping max-subtraction is mathematically identical to the reference softmax.
__global__ void k_colsum() {
    int j  = blockIdx.x * 256 + threadIdx.x;
    int r0 = blockIdx.y * 256;
    const float* p = g_S + (size_t)r0 * NN + j;
    float d = 0.f;
    for (int r = 0; r < 256; r += 8) {
        float v[8];
#pragma unroll
        for (int u = 0; u < 8; u++) v[u] = p[(size_t)(r + u) * NN];
#pragma unroll
        for (int u = 0; u < 8; u++) d += __expf(v[u]);
    }
    g_dpart[blockIdx.y * NN + j] = d;
}

__global__ void k_invd() {
    int j = blockIdx.x * 256 + threadIdx.x;
    float d = 0.f;
#pragma unroll
    for (int s = 0; s < 32; s++) d += g_dpart[s * NN + j];
    g_invD[j] = 1.0f / d;
}

// ---------------- K4: out = exp(S) @ (xe * invD), K split into 8 slices -------
__global__ __launch_bounds__(256) void k_av() {
    __shared__ float Ps[32][SPAD];   // [j][i] exp(S) tile, transposed
    __shared__ float vs[32][72];     // [j][f] scaled value tile
    const int i0    = blockIdx.x * 128;
    const int jbase = blockIdx.y * 1024;
    const int t  = threadIdx.x;
    const int tx = t & 15, ty = t >> 4;
    const int jf4 = t & 7, rr = t >> 3;

    float acc[2][4][4];
#pragma unroll
    for (int a = 0; a < 2; a++)
#pragma unroll
        for (int r = 0; r < 4; r++)
#pragma unroll
            for (int c = 0; c < 4; c++) acc[a][r][c] = 0.f;

    for (int ch = 0; ch < 32; ch++) {
        int j0 = jbase + ch * 32;
        __syncthreads();
#pragma unroll
        for (int l = 0; l < 4; l++) {
            int row = rr + l * 32;
            float4 s = *(const float4*)(g_S + (size_t)(i0 + row) * NN + j0 + jf4 * 4);
            Ps[jf4 * 4 + 0][row] = __expf(s.x);
            Ps[jf4 * 4 + 1][row] = __expf(s.y);
            Ps[jf4 * 4 + 2][row] = __expf(s.z);
            Ps[jf4 * 4 + 3][row] = __expf(s.w);
        }
#pragma unroll
        for (int l = 0; l < 2; l++) {
            int q = t + l * 256;
            int jj = q >> 4, fp = q & 15;
            float inv = __ldg(g_invD + j0 + jj);
            float4 v = *(const float4*)(g_xe + (size_t)(j0 + jj) * FF + fp * 4);
            v.x *= inv; v.y *= inv; v.z *= inv; v.w *= inv;
            *(float4*)&vs[jj][fp * 4] = v;
        }
        __syncthreads();
#pragma unroll 4
        for (int jj = 0; jj < 32; jj++) {
            float p0[4], p1[4], vv[4];
            *(float4*)p0 = *(const float4*)&Ps[jj][ty * 4];
            *(float4*)p1 = *(const float4*)&Ps[jj][64 + ty * 4];
            *(float4*)vv = *(const float4*)&vs[jj][tx * 4];
#pragma unroll
            for (int r = 0; r < 4; r++)
#pragma unroll
                for (int c = 0; c < 4; c++) {
                    acc[0][r][c] += p0[r] * vv[c];
                    acc[1][r][c] += p1[r] * vv[c];
                }
        }
    }
    float* op = g_outpart + (size_t)blockIdx.y * NN * FF;
#pragma unroll
    for (int a = 0; a < 2; a++)
#pragma unroll
        for (int r = 0; r < 4; r++) {
            float4 v = make_float4(acc[a][r][0], acc[a][r][1], acc[a][r][2], acc[a][r][3]);
            *(float4*)(op + (size_t)(i0 + a * 64 + ty * 4 + r) * FF + tx * 4) = v;
        }
}

// ---------------- K4r: deterministic reduction of the 8 K-slices --------------
__global__ void k_reduce_out(float* __restrict__ out) {
    int q = blockIdx.x * 256 + threadIdx.x;      // float4 index < NN*FF/4
    float4 s = ((const float4*)g_outpart)[q];
#pragma unroll
    for (int p = 1; p < 8; p++) {
        float4 v = ((const float4*)(g_outpart + (size_t)p * NN * FF))[q];
        s.x += v.x; s.y += v.y; s.z += v.z; s.w += v.w;
    }
    ((float4*)out)[q] = s;
}

// ---------------- K5a: row sum-of-squares + column sums (partials) ------------
__global__ void k_stats(const float* __restrict__ out) {
    __shared__ float sh[256];
    int b = blockIdx.x, t = threadIdx.x;
    // phase A: per-row sum of squares
    const float4* row = (const float4*)(out + (size_t)(b * 256 + t) * FF);
    float ss = 0.f;
#pragma unroll
    for (int i = 0; i < 16; i++) {
        float4 v = row[i];
        ss += v.x * v.x + v.y * v.y + v.z * v.z + v.w * v.w;
    }
    sh[t] = ss;
    __syncthreads();
    for (int s = 128; s > 0; s >>= 1) {
        if (t < s) sh[t] += sh[t + s];
        __syncthreads();
    }
    if (t == 0) g_sumsq_part[b] = sh[0];
    __syncthreads();
    // phase B: column sums over this block's 256 rows
    int f = t & 63, g = t >> 6;
    float cs = 0.f;
    for (int r = 0; r < 64; r++) cs += out[(size_t)(b * 256 + g * 64 + r) * FF + f];
    sh[t] = cs;
    __syncthreads();
    if (t < 64) g_colsum_part[b * FF + t] = sh[t] + sh[t + 64] + sh[t + 128] + sh[t + 192];
}

// ---------------- K5b: final mean(E) + alpha/beta MLPs ------------------------
__global__ void k_final(float* __restrict__ out,
                        const float* __restrict__ wa1, const float* __restrict__ ba1,
                        const float* __restrict__ wa2, const float* __restrict__ ba2,
                        const float* __restrict__ wb1, const float* __restrict__ bb1,
                        const float* __restrict__ wb2, const float* __restrict__ bb2) {
    __shared__ float sh[64];
    int t = threadIdx.x;                 // 64 threads
    float cs = 0.f;
    for (int b = 0; b < 32; b++) cs += g_colsum_part[b * FF + t];
    sh[t] = cs * cs;
    __syncthreads();
    if (t == 0) {
        float s2 = 0.f;
        for (int i = 0; i < 64; i++) s2 += sh[i];
        float sq = 0.f;
        for (int b = 0; b < 32; b++) sq += g_sumsq_part[b];
        // mean(E) = 2*mean_i(sq_i) - (2/N^2) * sum_f colsum_f^2
        float m = 2.0f * sq / (float)NN - 2.0f * s2 / ((float)NN * (float)NN);
        // alpha MLP: 1->2->1, tanh after every linear
        float ha0 = tanhf(m * __ldg(wa1 + 0) + __ldg(ba1 + 0));
        float ha1 = tanhf(m * __ldg(wa1 + 1) + __ldg(ba1 + 1));
        float ao  = tanhf(ha0 * __ldg(wa2 + 0) + ha1 * __ldg(wa2 + 1) + __ldg(ba2));
        // beta MLP
        float hb0 = tanhf(m * __ldg(wb1 + 0) + __ldg(bb1 + 0));
        float hb1 = tanhf(m * __ldg(wb1 + 1) + __ldg(bb1 + 1));
        float bo  = tanhf(hb0 * __ldg(wb2 + 0) + hb1 * __ldg(wb2 + 1) + __ldg(bb2));
        out[NN * FF]     = expf(SLOPEC * ao);
        out[NN * FF + 1] = expf(-SLOPEC * bo);
    }
}

// ---------------- launch ------------------------------------------------------
extern "C" void kernel_launch(void* const* d_in, const int* in_sizes, int n_in,
                              void* d_out, int out_size) {
    const float* x     = (const float*)d_in[0];
    const float* w_in1 = (const float*)d_in[1];
    const float* b_in1 = (const float*)d_in[2];
    const float* w_in2 = (const float*)d_in[3];
    const float* b_in2 = (const float*)d_in[4];
    const float* w_in3 = (const float*)d_in[5];
    const float* b_in3 = (const float*)d_in[6];
    const float* w_a1  = (const float*)d_in[7];
    const float* b_a1  = (const float*)d_in[8];
    const float* w_a2  = (const float*)d_in[9];
    const float* b_a2  = (const float*)d_in[10];
    const float* w_b1  = (const float*)d_in[11];
    const float* b_b1  = (const float*)d_in[12];
    const float* w_b2  = (const float*)d_in[13];
    const float* b_b2  = (const float*)d_in[14];
    float* out = (float*)d_out;

    k_encode<<<NN * FF / 256, 256>>>(x, w_in1, b_in1, w_in2, b_in2, w_in3, b_in3);
    k_gemm_s<<<dim3(64, 64), 256>>>();
    k_colsum<<<dim3(32, 32), 256>>>();
    k_invd<<<32, 256>>>();
    k_av<<<dim3(64, 8), 256>>>();
    k_reduce_out<<<NN * FF / 4 / 256, 256>>>(out);
    k_stats<<<32, 256>>>(out);
    k_final<<<1, 64>>>(out, w_a1, b_a1, w_a2, b_a2, w_b1, b_b1, w_b2, b_b2);
}

// round 5
// speedup vs baseline: 1.0021x; 1.0021x over previous
#include <cuda_runtime.h>
#include <math.h>

#define NN 8192
#define FF 64
#define SLOPEC 3.0f

// ---------------- scratch (device globals; no allocations allowed) -------------
__device__ float g_xe[NN * FF];                      // encoded features (2 MB)
__device__ float g_S[(size_t)NN * NN];               // logits S = xe xe^T (256 MB)
__device__ float g_dpart[32 * NN];                   // partial column sums of exp(S)
__device__ float g_invD[NN];                         // 1 / column sum
__device__ float g_outpart[8 * NN * FF];             // K-split partials of attn@xe (16 MB)
__device__ float g_colsum_part[32 * FF];
__device__ float g_sumsq_part[32];

// ---------------- K1: per-element encoder MLP 2->4->4->1 (tanh each) ----------
__global__ void k_encode(const float* __restrict__ x,
                         const float* __restrict__ w1, const float* __restrict__ b1,
                         const float* __restrict__ w2, const float* __restrict__ b2,
                         const float* __restrict__ w3, const float* __restrict__ b3) {
    int idx = blockIdx.x * 256 + threadIdx.x;        // < NN*FF
    float2 xv = ((const float2*)x)[idx];
    float h1[4], h2[4];
#pragma unroll
    for (int j = 0; j < 4; j++)
        h1[j] = tanhf(xv.x * __ldg(w1 + j) + xv.y * __ldg(w1 + 4 + j) + __ldg(b1 + j));
#pragma unroll
    for (int j = 0; j < 4; j++)
        h2[j] = tanhf(h1[0] * __ldg(w2 + j) + h1[1] * __ldg(w2 + 4 + j) +
                      h1[2] * __ldg(w2 + 8 + j) + h1[3] * __ldg(w2 + 12 + j) + __ldg(b2 + j));
    float o = tanhf(h2[0] * __ldg(w3 + 0) + h2[1] * __ldg(w3 + 1) +
                    h2[2] * __ldg(w3 + 2) + h2[3] * __ldg(w3 + 3) + __ldg(b3));
    g_xe[idx] = o;
}

// ---------------- K2: S = xe * xe^T  (fp32, 128x128 tile, K=64) ---------------
#define SPAD 132   // padded tile row length; 132*4 bytes is 16B-aligned, reduces STS conflicts
__global__ __launch_bounds__(256, 2) void k_gemm_s() {
    __shared__ float sa[32][SPAD];   // [k][m] transposed A tile (i rows)
    __shared__ float sb[32][SPAD];   // [k][n] transposed A tile (j rows)
    const int i0 = blockIdx.y * 128;
    const int j0 = blockIdx.x * 128;
    const int t  = threadIdx.x;
    const int tx = t & 15, ty = t >> 4;
    const int kf4 = t & 7, rr = t >> 3;     // load mapping: 8 f4 per k-row, 32 row groups

    float acc[2][2][4][4];
#pragma unroll
    for (int a = 0; a < 2; a++)
#pragma unroll
        for (int b = 0; b < 2; b++)
#pragma unroll
            for (int r = 0; r < 4; r++)
#pragma unroll
                for (int c = 0; c < 4; c++) acc[a][b][r][c] = 0.f;

    for (int kb = 0; kb < 64; kb += 32) {
        __syncthreads();
#pragma unroll
        for (int l = 0; l < 4; l++) {
            int row = rr + l * 32;
            float4 va = *(const float4*)(g_xe + (size_t)(i0 + row) * FF + kb + kf4 * 4);
            sa[kf4 * 4 + 0][row] = va.x; sa[kf4 * 4 + 1][row] = va.y;
            sa[kf4 * 4 + 2][row] = va.z; sa[kf4 * 4 + 3][row] = va.w;
            float4 vb = *(const float4*)(g_xe + (size_t)(j0 + row) * FF + kb + kf4 * 4);
            sb[kf4 * 4 + 0][row] = vb.x; sb[kf4 * 4 + 1][row] = vb.y;
            sb[kf4 * 4 + 2][row] = vb.z; sb[kf4 * 4 + 3][row] = vb.w;
        }
        __syncthreads();
#pragma unroll 4
        for (int k = 0; k < 32; k++) {
            float a0[4], a1[4], b0[4], b1[4];
            *(float4*)a0 = *(const float4*)&sa[k][ty * 4];
            *(float4*)a1 = *(const float4*)&sa[k][64 + ty * 4];
            *(float4*)b0 = *(const float4*)&sb[k][tx * 4];
            *(float4*)b1 = *(const float4*)&sb[k][64 + tx * 4];
#pragma unroll
            for (int r = 0; r < 4; r++)
#pragma unroll
                for (int c = 0; c < 4; c++) {
                    acc[0][0][r][c] += a0[r] * b0[c];
                    acc[0][1][r][c] += a0[r] * b1[c];
                    acc[1][0][r][c] += a1[r] * b0[c];
                    acc[1][1][r][c] += a1[r] * b1[c];
                }
        }
    }
#pragma unroll
    for (int a = 0; a < 2; a++)
#pragma unroll
        for (int r = 0; r < 4; r++) {
            size_t i = (size_t)(i0 + a * 64 + ty * 4 + r);
            float4 v0 = make_float4(acc[a][0][r][0], acc[a][0][r][1], acc[a][0][r][2], acc[a][0][r][3]);
            float4 v1 = make_float4(acc[a][1][r][0], acc[a][1][r][1], acc[a][1][r][2], acc[a][1][r][3]);
            *(float4*)(g_S + i * NN + j0 + tx * 4)      = v0;
            *(float4*)(g_S + i * NN + j0 + 64 + tx * 4) = v1;
        }
}

// ---------------- K3: partial column sums of exp(S) ---------------------------
// |S| < 64 strictly (tanh outputs), so exp(S) and its sums stay in fp32 range;
// skipping max-subtraction is mathematically identical to the reference softmax.
__global__ void k_colsum() {
    int j  = blockIdx.x * 256 + threadIdx.x;
    int r0 = blockIdx.y * 256;
    const float* p = g_S + (size_t)r0 * NN + j;
    float d = 0.f;
    for (int r = 0; r < 256; r += 8) {
        float v[8];
#pragma unroll
        for (int u = 0; u < 8; u++) v[u] = p[(size_t)(r + u) * NN];
#pragma unroll
        for (int u = 0; u < 8; u++) d += __expf(v[u]);
    }
    g_dpart[blockIdx.y * NN + j] = d;
}

__global__ void k_invd() {
    int j = blockIdx.x * 256 + threadIdx.x;
    float d = 0.f;
#pragma unroll
    for (int s = 0; s < 32; s++) d += g_dpart[s * NN + j];
    g_invD[j] = 1.0f / d;
}

// ---------------- K4: out = exp(S) @ (xe * invD), K split into 8 slices -------
__global__ __launch_bounds__(256) void k_av() {
    __shared__ float Ps[32][SPAD];   // [j][i] exp(S) tile, transposed
    __shared__ float vs[32][72];     // [j][f] scaled value tile
    const int i0    = blockIdx.x * 128;
    const int jbase = blockIdx.y * 1024;
    const int t  = threadIdx.x;
    const int tx = t & 15, ty = t >> 4;
    const int jf4 = t & 7, rr = t >> 3;

    float acc[2][4][4];
#pragma unroll
    for (int a = 0; a < 2; a++)
#pragma unroll
        for (int r = 0; r < 4; r++)
#pragma unroll
            for (int c = 0; c < 4; c++) acc[a][r][c] = 0.f;

    for (int ch = 0; ch < 32; ch++) {
        int j0 = jbase + ch * 32;
        __syncthreads();
#pragma unroll
        for (int l = 0; l < 4; l++) {
            int row = rr + l * 32;
            float4 s = *(const float4*)(g_S + (size_t)(i0 + row) * NN + j0 + jf4 * 4);
            Ps[jf4 * 4 + 0][row] = __expf(s.x);
            Ps[jf4 * 4 + 1][row] = __expf(s.y);
            Ps[jf4 * 4 + 2][row] = __expf(s.z);
            Ps[jf4 * 4 + 3][row] = __expf(s.w);
        }
#pragma unroll
        for (int l = 0; l < 2; l++) {
            int q = t + l * 256;
            int jj = q >> 4, fp = q & 15;
            float inv = __ldg(g_invD + j0 + jj);
            float4 v = *(const float4*)(g_xe + (size_t)(j0 + jj) * FF + fp * 4);
            v.x *= inv; v.y *= inv; v.z *= inv; v.w *= inv;
            *(float4*)&vs[jj][fp * 4] = v;
        }
        __syncthreads();
#pragma unroll 4
        for (int jj = 0; jj < 32; jj++) {
            float p0[4], p1[4], vv[4];
            *(float4*)p0 = *(const float4*)&Ps[jj][ty * 4];
            *(float4*)p1 = *(const float4*)&Ps[jj][64 + ty * 4];
            *(float4*)vv = *(const float4*)&vs[jj][tx * 4];
#pragma unroll
            for (int r = 0; r < 4; r++)
#pragma unroll
                for (int c = 0; c < 4; c++) {
                    acc[0][r][c] += p0[r] * vv[c];
                    acc[1][r][c] += p1[r] * vv[c];
                }
        }
    }
    float* op = g_outpart + (size_t)blockIdx.y * NN * FF;
#pragma unroll
    for (int a = 0; a < 2; a++)
#pragma unroll
        for (int r = 0; r < 4; r++) {
            float4 v = make_float4(acc[a][r][0], acc[a][r][1], acc[a][r][2], acc[a][r][3]);
            *(float4*)(op + (size_t)(i0 + a * 64 + ty * 4 + r) * FF + tx * 4) = v;
        }
}

// ---------------- K4r: deterministic reduction of the 8 K-slices --------------
__global__ void k_reduce_out(float* __restrict__ out) {
    int q = blockIdx.x * 256 + threadIdx.x;      // float4 index < NN*FF/4
    float4 s = ((const float4*)g_outpart)[q];
#pragma unroll
    for (int p = 1; p < 8; p++) {
        float4 v = ((const float4*)(g_outpart + (size_t)p * NN * FF))[q];
        s.x += v.x; s.y += v.y; s.z += v.z; s.w += v.w;
    }
    ((float4*)out)[q] = s;
}

// ---------------- K5a: row sum-of-squares + column sums (partials) ------------
__global__ void k_stats(const float* __restrict__ out) {
    __shared__ float sh[256];
    int b = blockIdx.x, t = threadIdx.x;
    // phase A: per-row sum of squares
    const float4* row = (const float4*)(out + (size_t)(b * 256 + t) * FF);
    float ss = 0.f;
#pragma unroll
    for (int i = 0; i < 16; i++) {
        float4 v = row[i];
        ss += v.x * v.x + v.y * v.y + v.z * v.z + v.w * v.w;
    }
    sh[t] = ss;
    __syncthreads();
    for (int s = 128; s > 0; s >>= 1) {
        if (t < s) sh[t] += sh[t + s];
        __syncthreads();
    }
    if (t == 0) g_sumsq_part[b] = sh[0];
    __syncthreads();
    // phase B: column sums over this block's 256 rows
    int f = t & 63, g = t >> 6;
    float cs = 0.f;
    for (int r = 0; r < 64; r++) cs += out[(size_t)(b * 256 + g * 64 + r) * FF + f];
    sh[t] = cs;
    __syncthreads();
    if (t < 64) g_colsum_part[b * FF + t] = sh[t] + sh[t + 64] + sh[t + 128] + sh[t + 192];
}

// ---------------- K5b: final mean(E) + alpha/beta MLPs ------------------------
__global__ void k_final(float* __restrict__ out,
                        const float* __restrict__ wa1, const float* __restrict__ ba1,
                        const float* __restrict__ wa2, const float* __restrict__ ba2,
                        const float* __restrict__ wb1, const float* __restrict__ bb1,
                        const float* __restrict__ wb2, const float* __restrict__ bb2) {
    __shared__ float sh[64];
    int t = threadIdx.x;                 // 64 threads
    float cs = 0.f;
    for (int b = 0; b < 32; b++) cs += g_colsum_part[b * FF + t];
    sh[t] = cs * cs;
    __syncthreads();
    if (t == 0) {
        float s2 = 0.f;
        for (int i = 0; i < 64; i++) s2 += sh[i];
        float sq = 0.f;
        for (int b = 0; b < 32; b++) sq += g_sumsq_part[b];
        // mean(E) = 2*mean_i(sq_i) - (2/N^2) * sum_f colsum_f^2
        float m = 2.0f * sq / (float)NN - 2.0f * s2 / ((float)NN * (float)NN);
        // alpha MLP: 1->2->1, tanh after every linear
        float ha0 = tanhf(m * __ldg(wa1 + 0) + __ldg(ba1 + 0));
        float ha1 = tanhf(m * __ldg(wa1 + 1) + __ldg(ba1 + 1));
        float ao  = tanhf(ha0 * __ldg(wa2 + 0) + ha1 * __ldg(wa2 + 1) + __ldg(ba2));
        // beta MLP
        float hb0 = tanhf(m * __ldg(wb1 + 0) + __ldg(bb1 + 0));
        float hb1 = tanhf(m * __ldg(wb1 + 1) + __ldg(bb1 + 1));
        float bo  = tanhf(hb0 * __ldg(wb2 + 0) + hb1 * __ldg(wb2 + 1) + __ldg(bb2));
        out[NN * FF]     = expf(SLOPEC * ao);
        out[NN * FF + 1] = expf(-SLOPEC * bo);
    }
}

// ---------------- launch ------------------------------------------------------
extern "C" void kernel_launch(void* const* d_in, const int* in_sizes, int n_in,
                              void* d_out, int out_size) {
    const float* x     = (const float*)d_in[0];
    const float* w_in1 = (const float*)d_in[1];
    const float* b_in1 = (const float*)d_in[2];
    const float* w_in2 = (const float*)d_in[3];
    const float* b_in2 = (const float*)d_in[4];
    const float* w_in3 = (const float*)d_in[5];
    const float* b_in3 = (const float*)d_in[6];
    const float* w_a1  = (const float*)d_in[7];
    const float* b_a1  = (const float*)d_in[8];
    const float* w_a2  = (const float*)d_in[9];
    const float* b_a2  = (const float*)d_in[10];
    const float* w_b1  = (const float*)d_in[11];
    const float* b_b1  = (const float*)d_in[12];
    const float* w_b2  = (const float*)d_in[13];
    const float* b_b2  = (const float*)d_in[14];
    float* out = (float*)d_out;

    k_encode<<<NN * FF / 256, 256>>>(x, w_in1, b_in1, w_in2, b_in2, w_in3, b_in3);
    k_gemm_s<<<dim3(64, 64), 256>>>();
    k_colsum<<<dim3(32, 32), 256>>>();
    k_invd<<<32, 256>>>();
    k_av<<<dim3(64, 8), 256>>>();
    k_reduce_out<<<NN * FF / 4 / 256, 256>>>(out);
    k_stats<<<32, 256>>>(out);
    k_final<<<1, 64>>>(out, w_a1, b_a1, w_a2, b_a2, w_b1, b_b1, w_b2, b_b2);
}

// round 6
// speedup vs baseline: 1.0030x; 1.0009x over previous
#include <cuda_runtime.h>
#include <math.h>

#define NN 8192
#define FF 64
#define SLOPEC 3.0f

// ---------------- scratch (device globals; no allocations allowed) -------------
__device__ float g_xe[NN * FF];                      // encoded features (2 MB)
__device__ float g_S[(size_t)NN * NN];               // logits S = xe xe^T (256 MB)
__device__ float g_dpart[32 * NN];                   // partial column sums of exp(S)
__device__ float g_invD[NN];                         // 1 / column sum
__device__ float g_outpart[8 * NN * FF];             // K-split partials of attn@xe (16 MB)
__device__ float g_colsum_part[32 * FF];
__device__ float g_sumsq_part[32];

// ---------------- K1: per-element encoder MLP 2->4->4->1 (tanh each) ----------
__global__ void k_encode(const float* __restrict__ x,
                         const float* __restrict__ w1, const float* __restrict__ b1,
                         const float* __restrict__ w2, const float* __restrict__ b2,
                         const float* __restrict__ w3, const float* __restrict__ b3) {
    int idx = blockIdx.x * 256 + threadIdx.x;        // < NN*FF
    float2 xv = ((const float2*)x)[idx];
    float h1[4], h2[4];
#pragma unroll
    for (int j = 0; j < 4; j++)
        h1[j] = tanhf(xv.x * __ldg(w1 + j) + xv.y * __ldg(w1 + 4 + j) + __ldg(b1 + j));
#pragma unroll
    for (int j = 0; j < 4; j++)
        h2[j] = tanhf(h1[0] * __ldg(w2 + j) + h1[1] * __ldg(w2 + 4 + j) +
                      h1[2] * __ldg(w2 + 8 + j) + h1[3] * __ldg(w2 + 12 + j) + __ldg(b2 + j));
    float o = tanhf(h2[0] * __ldg(w3 + 0) + h2[1] * __ldg(w3 + 1) +
                    h2[2] * __ldg(w3 + 2) + h2[3] * __ldg(w3 + 3) + __ldg(b3));
    g_xe[idx] = o;
}

// ---------------- K2: S = xe * xe^T  (fp32, 128x128 tile, K=64) ---------------
#define SPAD 132   // padded tile row length; 132*4 bytes is 16B-aligned, reduces STS conflicts
__global__ __launch_bounds__(256, 2) void k_gemm_s() {
    __shared__ float sa[32][SPAD];   // [k][m] transposed A tile (i rows)
    __shared__ float sb[32][SPAD];   // [k][n] transposed A tile (j rows)
    const int i0 = blockIdx.y * 128;
    const int j0 = blockIdx.x * 128;
    const int t  = threadIdx.x;
    const int tx = t & 15, ty = t >> 4;
    const int kf4 = t & 7, rr = t >> 3;     // load mapping: 8 f4 per k-row, 32 row groups

    float acc[2][2][4][4];
#pragma unroll
    for (int a = 0; a < 2; a++)
#pragma unroll
        for (int b = 0; b < 2; b++)
#pragma unroll
            for (int r = 0; r < 4; r++)
#pragma unroll
                for (int c = 0; c < 4; c++) acc[a][b][r][c] = 0.f;

    for (int kb = 0; kb < 64; kb += 32) {
        __syncthreads();
#pragma unroll
        for (int l = 0; l < 4; l++) {
            int row = rr + l * 32;
            float4 va = *(const float4*)(g_xe + (size_t)(i0 + row) * FF + kb + kf4 * 4);
            sa[kf4 * 4 + 0][row] = va.x; sa[kf4 * 4 + 1][row] = va.y;
            sa[kf4 * 4 + 2][row] = va.z; sa[kf4 * 4 + 3][row] = va.w;
            float4 vb = *(const float4*)(g_xe + (size_t)(j0 + row) * FF + kb + kf4 * 4);
            sb[kf4 * 4 + 0][row] = vb.x; sb[kf4 * 4 + 1][row] = vb.y;
            sb[kf4 * 4 + 2][row] = vb.z; sb[kf4 * 4 + 3][row] = vb.w;
        }
        __syncthreads();
#pragma unroll 4
        for (int k = 0; k < 32; k++) {
            float a0[4], a1[4], b0[4], b1[4];
            *(float4*)a0 = *(const float4*)&sa[k][ty * 4];
            *(float4*)a1 = *(const float4*)&sa[k][64 + ty * 4];
            *(float4*)b0 = *(const float4*)&sb[k][tx * 4];
            *(float4*)b1 = *(const float4*)&sb[k][64 + tx * 4];
#pragma unroll
            for (int r = 0; r < 4; r++)
#pragma unroll
                for (int c = 0; c < 4; c++) {
                    acc[0][0][r][c] += a0[r] * b0[c];
                    acc[0][1][r][c] += a0[r] * b1[c];
                    acc[1][0][r][c] += a1[r] * b0[c];
                    acc[1][1][r][c] += a1[r] * b1[c];
                }
        }
    }
#pragma unroll
    for (int a = 0; a < 2; a++)
#pragma unroll
        for (int r = 0; r < 4; r++) {
            size_t i = (size_t)(i0 + a * 64 + ty * 4 + r);
            float4 v0 = make_float4(acc[a][0][r][0], acc[a][0][r][1], acc[a][0][r][2], acc[a][0][r][3]);
            float4 v1 = make_float4(acc[a][1][r][0], acc[a][1][r][1], acc[a][1][r][2], acc[a][1][r][3]);
            *(float4*)(g_S + i * NN + j0 + tx * 4)      = v0;
            *(float4*)(g_S + i * NN + j0 + 64 + tx * 4) = v1;
        }
}

// ---------------- K3: partial column sums of exp(S) ---------------------------
// |S| < 64 strictly (tanh outputs), so exp(S) and its sums stay in fp32 range;
// skipping max-subtraction is mathematically identical to the reference softmax.
__global__ void k_colsum() {
    int j  = blockIdx.x * 256 + threadIdx.x;
    int r0 = blockIdx.y * 256;
    const float* p = g_S + (size_t)r0 * NN + j;
    float d = 0.f;
    for (int r = 0; r < 256; r += 8) {
        float v[8];
#pragma unroll
        for (int u = 0; u < 8; u++) v[u] = p[(size_t)(r + u) * NN];
#pragma unroll
        for (int u = 0; u < 8; u++) d += __expf(v[u]);
    }
    g_dpart[blockIdx.y * NN + j] = d;
}

__global__ void k_invd() {
    int j = blockIdx.x * 256 + threadIdx.x;
    float d = 0.f;
#pragma unroll
    for (int s = 0; s < 32; s++) d += g_dpart[s * NN + j];
    g_invD[j] = 1.0f / d;
}

// ---------------- K4: out = exp(S) @ (xe * invD), K split into 8 slices -------
__global__ __launch_bounds__(256) void k_av() {
    __shared__ float Ps[32][SPAD];   // [j][i] exp(S) tile, transposed
    __shared__ float vs[32][72];     // [j][f] scaled value tile
    const int i0    = blockIdx.x * 128;
    const int jbase = blockIdx.y * 1024;
    const int t  = threadIdx.x;
    const int tx = t & 15, ty = t >> 4;
    const int jf4 = t & 7, rr = t >> 3;

    float acc[2][4][4];
#pragma unroll
    for (int a = 0; a < 2; a++)
#pragma unroll
        for (int r = 0; r < 4; r++)
#pragma unroll
            for (int c = 0; c < 4; c++) acc[a][r][c] = 0.f;

    for (int ch = 0; ch < 32; ch++) {
        int j0 = jbase + ch * 32;
        __syncthreads();
#pragma unroll
        for (int l = 0; l < 4; l++) {
            int row = rr + l * 32;
            float4 s = *(const float4*)(g_S + (size_t)(i0 + row) * NN + j0 + jf4 * 4);
            Ps[jf4 * 4 + 0][row] = __expf(s.x);
            Ps[jf4 * 4 + 1][row] = __expf(s.y);
            Ps[jf4 * 4 + 2][row] = __expf(s.z);
            Ps[jf4 * 4 + 3][row] = __expf(s.w);
        }
#pragma unroll
        for (int l = 0; l < 2; l++) {
            int q = t + l * 256;
            int jj = q >> 4, fp = q & 15;
            float inv = __ldg(g_invD + j0 + jj);
            float4 v = *(const float4*)(g_xe + (size_t)(j0 + jj) * FF + fp * 4);
            v.x *= inv; v.y *= inv; v.z *= inv; v.w *= inv;
            *(float4*)&vs[jj][fp * 4] = v;
        }
        __syncthreads();
#pragma unroll 4
        for (int jj = 0; jj < 32; jj++) {
            float p0[4], p1[4], vv[4];
            *(float4*)p0 = *(const float4*)&Ps[jj][ty * 4];
            *(float4*)p1 = *(const float4*)&Ps[jj][64 + ty * 4];
            *(float4*)vv = *(const float4*)&vs[jj][tx * 4];
#pragma unroll
            for (int r = 0; r < 4; r++)
#pragma unroll
                for (int c = 0; c < 4; c++) {
                    acc[0][r][c] += p0[r] * vv[c];
                    acc[1][r][c] += p1[r] * vv[c];
                }
        }
    }
    float* op = g_outpart + (size_t)blockIdx.y * NN * FF;
#pragma unroll
    for (int a = 0; a < 2; a++)
#pragma unroll
        for (int r = 0; r < 4; r++) {
            float4 v = make_float4(acc[a][r][0], acc[a][r][1], acc[a][r][2], acc[a][r][3]);
            *(float4*)(op + (size_t)(i0 + a * 64 + ty * 4 + r) * FF + tx * 4) = v;
        }
}

// ---------------- K4r: deterministic reduction of the 8 K-slices --------------
__global__ void k_reduce_out(float* __restrict__ out) {
    int q = blockIdx.x * 256 + threadIdx.x;      // float4 index < NN*FF/4
    float4 s = ((const float4*)g_outpart)[q];
#pragma unroll
    for (int p = 1; p < 8; p++) {
        float4 v = ((const float4*)(g_outpart + (size_t)p * NN * FF))[q];
        s.x += v.x; s.y += v.y; s.z += v.z; s.w += v.w;
    }
    ((float4*)out)[q] = s;
}

// ---------------- K5a: row sum-of-squares + column sums (partials) ------------
__global__ void k_stats(const float* __restrict__ out) {
    __shared__ float sh[256];
    int b = blockIdx.x, t = threadIdx.x;
    // phase A: per-row sum of squares
    const float4* row = (const float4*)(out + (size_t)(b * 256 + t) * FF);
    float ss = 0.f;
#pragma unroll
    for (int i = 0; i < 16; i++) {
        float4 v = row[i];
        ss += v.x * v.x + v.y * v.y + v.z * v.z + v.w * v.w;
    }
    sh[t] = ss;
    __syncthreads();
    for (int s = 128; s > 0; s >>= 1) {
        if (t < s) sh[t] += sh[t + s];
        __syncthreads();
    }
    if (t == 0) g_sumsq_part[b] = sh[0];
    __syncthreads();
    // phase B: column sums over this block's 256 rows
    int f = t & 63, g = t >> 6;
    float cs = 0.f;
    for (int r = 0; r < 64; r++) cs += out[(size_t)(b * 256 + g * 64 + r) * FF + f];
    sh[t] = cs;
    __syncthreads();
    if (t < 64) g_colsum_part[b * FF + t] = sh[t] + sh[t + 64] + sh[t + 128] + sh[t + 192];
}

// ---------------- K5b: final mean(E) + alpha/beta MLPs ------------------------
__global__ void k_final(float* __restrict__ out,
                        const float* __restrict__ wa1, const float* __restrict__ ba1,
                        const float* __restrict__ wa2, const float* __restrict__ ba2,
                        const float* __restrict__ wb1, const float* __restrict__ bb1,
                        const float* __restrict__ wb2, const float* __restrict__ bb2) {
    __shared__ float sh[64];
    int t = threadIdx.x;                 // 64 threads
    float cs = 0.f;
    for (int b = 0; b < 32; b++) cs += g_colsum_part[b * FF + t];
    sh[t] = cs * cs;
    __syncthreads();
    if (t == 0) {
        float s2 = 0.f;
        for (int i = 0; i < 64; i++) s2 += sh[i];
        float sq = 0.f;
        for (int b = 0; b < 32; b++) sq += g_sumsq_part[b];
        // mean(E) = 2*mean_i(sq_i) - (2/N^2) * sum_f colsum_f^2
        float m = 2.0f * sq / (float)NN - 2.0f * s2 / ((float)NN * (float)NN);
        // alpha MLP: 1->2->1, tanh after every linear
        float ha0 = tanhf(m * __ldg(wa1 + 0) + __ldg(ba1 + 0));
        float ha1 = tanhf(m * __ldg(wa1 + 1) + __ldg(ba1 + 1));
        float ao  = tanhf(ha0 * __ldg(wa2 + 0) + ha1 * __ldg(wa2 + 1) + __ldg(ba2));
        // beta MLP
        float hb0 = tanhf(m * __ldg(wb1 + 0) + __ldg(bb1 + 0));
        float hb1 = tanhf(m * __ldg(wb1 + 1) + __ldg(bb1 + 1));
        float bo  = tanhf(hb0 * __ldg(wb2 + 0) + hb1 * __ldg(wb2 + 1) + __ldg(bb2));
        out[NN * FF]     = expf(SLOPEC * ao);
        out[NN * FF + 1] = expf(-SLOPEC * bo);
    }
}

// ---------------- launch ------------------------------------------------------
extern "C" void kernel_launch(void* const* d_in, const int* in_sizes, int n_in,
                              void* d_out, int out_size) {
    const float* x     = (const float*)d_in[0];
    const float* w_in1 = (const float*)d_in[1];
    const float* b_in1 = (const float*)d_in[2];
    const float* w_in2 = (const float*)d_in[3];
    const float* b_in2 = (const float*)d_in[4];
    const float* w_in3 = (const float*)d_in[5];
    const float* b_in3 = (const float*)d_in[6];
    const float* w_a1  = (const float*)d_in[7];
    const float* b_a1  = (const float*)d_in[8];
    const float* w_a2  = (const float*)d_in[9];
    const float* b_a2  = (const float*)d_in[10];
    const float* w_b1  = (const float*)d_in[11];
    const float* b_b1  = (const float*)d_in[12];
    const float* w_b2  = (const float*)d_in[13];
    const float* b_b2  = (const float*)d_in[14];
    float* out = (float*)d_out;

    k_encode<<<NN * FF / 256, 256>>>(x, w_in1, b_in1, w_in2, b_in2, w_in3, b_in3);
    k_gemm_s<<<dim3(64, 64), 256>>>();
    k_colsum<<<dim3(32, 32), 256>>>();
    k_invd<<<32, 256>>>();
    k_av<<<dim3(64, 8), 256>>>();
    k_reduce_out<<<NN * FF / 4 / 256, 256>>>(out);
    k_stats<<<32, 256>>>(out);
    k_final<<<1, 64>>>(out, w_a1, b_a1, w_a2, b_a2, w_b1, b_b1, w_b2, b_b2);
}

// round 7
// speedup vs baseline: 1.0040x; 1.0011x over previous
#include <cuda_runtime.h>
#include <math.h>

#define NN 8192
#define FF 64
#define SLOPEC 3.0f

// ---------------- scratch (device globals; no allocations allowed) -------------
__device__ float g_xe[NN * FF];                      // encoded features (2 MB)
__device__ float g_S[(size_t)NN * NN];               // logits S = xe xe^T (256 MB)
__device__ float g_dpart[32 * NN];                   // partial column sums of exp(S)
__device__ float g_invD[NN];                         // 1 / column sum
__device__ float g_outpart[8 * NN * FF];             // K-split partials of attn@xe (16 MB)
__device__ float g_colsum_part[32 * FF];
__device__ float g_sumsq_part[32];

// ---------------- K1: per-element encoder MLP 2->4->4->1 (tanh each) ----------
__global__ void k_encode(const float* __restrict__ x,
                         const float* __restrict__ w1, const float* __restrict__ b1,
                         const float* __restrict__ w2, const float* __restrict__ b2,
                         const float* __restrict__ w3, const float* __restrict__ b3) {
    int idx = blockIdx.x * 256 + threadIdx.x;        // < NN*FF
    float2 xv = ((const float2*)x)[idx];
    float h1[4], h2[4];
#pragma unroll
    for (int j = 0; j < 4; j++)
        h1[j] = tanhf(xv.x * __ldg(w1 + j) + xv.y * __ldg(w1 + 4 + j) + __ldg(b1 + j));
#pragma unroll
    for (int j = 0; j < 4; j++)
        h2[j] = tanhf(h1[0] * __ldg(w2 + j) + h1[1] * __ldg(w2 + 4 + j) +
                      h1[2] * __ldg(w2 + 8 + j) + h1[3] * __ldg(w2 + 12 + j) + __ldg(b2 + j));
    float o = tanhf(h2[0] * __ldg(w3 + 0) + h2[1] * __ldg(w3 + 1) +
                    h2[2] * __ldg(w3 + 2) + h2[3] * __ldg(w3 + 3) + __ldg(b3));
    g_xe[idx] = o;
}

// ---------------- K2: S = xe * xe^T  (fp32, 128x128 tile, K=64) ---------------
#define SPAD 132   // padded tile row length; 132*4 bytes is 16B-aligned, reduces STS conflicts
__global__ __launch_bounds__(256, 2) void k_gemm_s() {
    __shared__ float sa[32][SPAD];   // [k][m] transposed A tile (i rows)
    __shared__ float sb[32][SPAD];   // [k][n] transposed A tile (j rows)
    const int i0 = blockIdx.y * 128;
    const int j0 = blockIdx.x * 128;
    const int t  = threadIdx.x;
    const int tx = t & 15, ty = t >> 4;
    const int kf4 = t & 7, rr = t >> 3;     // load mapping: 8 f4 per k-row, 32 row groups

    float acc[2][2][4][4];
#pragma unroll
    for (int a = 0; a < 2; a++)
#pragma unroll
        for (int b = 0; b < 2; b++)
#pragma unroll
            for (int r = 0; r < 4; r++)
#pragma unroll
                for (int c = 0; c < 4; c++) acc[a][b][r][c] = 0.f;

    for (int kb = 0; kb < 64; kb += 32) {
        __syncthreads();
#pragma unroll
        for (int l = 0; l < 4; l++) {
            int row = rr + l * 32;
            float4 va = *(const float4*)(g_xe + (size_t)(i0 + row) * FF + kb + kf4 * 4);
            sa[kf4 * 4 + 0][row] = va.x; sa[kf4 * 4 + 1][row] = va.y;
            sa[kf4 * 4 + 2][row] = va.z; sa[kf4 * 4 + 3][row] = va.w;
            float4 vb = *(const float4*)(g_xe + (size_t)(j0 + row) * FF + kb + kf4 * 4);
            sb[kf4 * 4 + 0][row] = vb.x; sb[kf4 * 4 + 1][row] = vb.y;
            sb[kf4 * 4 + 2][row] = vb.z; sb[kf4 * 4 + 3][row] = vb.w;
        }
        __syncthreads();
#pragma unroll 4
        for (int k = 0; k < 32; k++) {
            float a0[4], a1[4], b0[4], b1[4];
            *(float4*)a0 = *(const float4*)&sa[k][ty * 4];
            *(float4*)a1 = *(const float4*)&sa[k][64 + ty * 4];
            *(float4*)b0 = *(const float4*)&sb[k][tx * 4];
            *(float4*)b1 = *(const float4*)&sb[k][64 + tx * 4];
#pragma unroll
            for (int r = 0; r < 4; r++)
#pragma unroll
                for (int c = 0; c < 4; c++) {
                    acc[0][0][r][c] += a0[r] * b0[c];
                    acc[0][1][r][c] += a0[r] * b1[c];
                    acc[1][0][r][c] += a1[r] * b0[c];
                    acc[1][1][r][c] += a1[r] * b1[c];
                }
        }
    }
#pragma unroll
    for (int a = 0; a < 2; a++)
#pragma unroll
        for (int r = 0; r < 4; r++) {
            size_t i = (size_t)(i0 + a * 64 + ty * 4 + r);
            float4 v0 = make_float4(acc[a][0][r][0], acc[a][0][r][1], acc[a][0][r][2], acc[a][0][r][3]);
            float4 v1 = make_float4(acc[a][1][r][0], acc[a][1][r][1], acc[a][1][r][2], acc[a][1][r][3]);
            *(float4*)(g_S + i * NN + j0 + tx * 4)      = v0;
            *(float4*)(g_S + i * NN + j0 + 64 + tx * 4) = v1;
        }
}

// ---------------- K3: partial column sums of exp(S) ---------------------------
// |S| < 64 strictly (tanh outputs), so exp(S) and its sums stay in fp32 range;
// skipping max-subtraction is mathematically identical to the reference softmax.
__global__ void k_colsum() {
    int j  = blockIdx.x * 256 + threadIdx.x;
    int r0 = blockIdx.y * 256;
    const float* p = g_S + (size_t)r0 * NN + j;
    float d = 0.f;
    for (int r = 0; r < 256; r += 8) {
        float v[8];
#pragma unroll
        for (int u = 0; u < 8; u++) v[u] = p[(size_t)(r + u) * NN];
#pragma unroll
        for (int u = 0; u < 8; u++) d += __expf(v[u]);
    }
    g_dpart[blockIdx.y * NN + j] = d;
}

__global__ void k_invd() {
    int j = blockIdx.x * 256 + threadIdx.x;
    float d = 0.f;
#pragma unroll
    for (int s = 0; s < 32; s++) d += g_dpart[s * NN + j];
    g_invD[j] = 1.0f / d;
}

// ---------------- K4: out = exp(S) @ (xe * invD), K split into 8 slices -------
__global__ __launch_bounds__(256) void k_av() {
    __shared__ float Ps[32][SPAD];   // [j][i] exp(S) tile, transposed
    __shared__ float vs[32][72];     // [j][f] scaled value tile
    const int i0    = blockIdx.x * 128;
    const int jbase = blockIdx.y * 1024;
    const int t  = threadIdx.x;
    const int tx = t & 15, ty = t >> 4;
    const int jf4 = t & 7, rr = t >> 3;

    float acc[2][4][4];
#pragma unroll
    for (int a = 0; a < 2; a++)
#pragma unroll
        for (int r = 0; r < 4; r++)
#pragma unroll
            for (int c = 0; c < 4; c++) acc[a][r][c] = 0.f;

    for (int ch = 0; ch < 32; ch++) {
        int j0 = jbase + ch * 32;
        __syncthreads();
#pragma unroll
        for (int l = 0; l < 4; l++) {
            int row = rr + l * 32;
            float4 s = *(const float4*)(g_S + (size_t)(i0 + row) * NN + j0 + jf4 * 4);
            Ps[jf4 * 4 + 0][row] = __expf(s.x);
            Ps[jf4 * 4 + 1][row] = __expf(s.y);
            Ps[jf4 * 4 + 2][row] = __expf(s.z);
            Ps[jf4 * 4 + 3][row] = __expf(s.w);
        }
#pragma unroll
        for (int l = 0; l < 2; l++) {
            int q = t + l * 256;
            int jj = q >> 4, fp = q & 15;
            float inv = __ldg(g_invD + j0 + jj);
            float4 v = *(const float4*)(g_xe + (size_t)(j0 + jj) * FF + fp * 4);
            v.x *= inv; v.y *= inv; v.z *= inv; v.w *= inv;
            *(float4*)&vs[jj][fp * 4] = v;
        }
        __syncthreads();
#pragma unroll 4
        for (int jj = 0; jj < 32; jj++) {
            float p0[4], p1[4], vv[4];
            *(float4*)p0 = *(const float4*)&Ps[jj][ty * 4];
            *(float4*)p1 = *(const float4*)&Ps[jj][64 + ty * 4];
            *(float4*)vv = *(const float4*)&vs[jj][tx * 4];
#pragma unroll
            for (int r = 0; r < 4; r++)
#pragma unroll
                for (int c = 0; c < 4; c++) {
                    acc[0][r][c] += p0[r] * vv[c];
                    acc[1][r][c] += p1[r] * vv[c];
                }
        }
    }
    float* op = g_outpart + (size_t)blockIdx.y * NN * FF;
#pragma unroll
    for (int a = 0; a < 2; a++)
#pragma unroll
        for (int r = 0; r < 4; r++) {
            float4 v = make_float4(acc[a][r][0], acc[a][r][1], acc[a][r][2], acc[a][r][3]);
            *(float4*)(op + (size_t)(i0 + a * 64 + ty * 4 + r) * FF + tx * 4) = v;
        }
}

// ---------------- K4r: deterministic reduction of the 8 K-slices --------------
__global__ void k_reduce_out(float* __restrict__ out) {
    int q = blockIdx.x * 256 + threadIdx.x;      // float4 index < NN*FF/4
    float4 s = ((const float4*)g_outpart)[q];
#pragma unroll
    for (int p = 1; p < 8; p++) {
        float4 v = ((const float4*)(g_outpart + (size_t)p * NN * FF))[q];
        s.x += v.x; s.y += v.y; s.z += v.z; s.w += v.w;
    }
    ((float4*)out)[q] = s;
}

// ---------------- K5a: row sum-of-squares + column sums (partials) ------------
__global__ void k_stats(const float* __restrict__ out) {
    __shared__ float sh[256];
    int b = blockIdx.x, t = threadIdx.x;
    // phase A: per-row sum of squares
    const float4* row = (const float4*)(out + (size_t)(b * 256 + t) * FF);
    float ss = 0.f;
#pragma unroll
    for (int i = 0; i < 16; i++) {
        float4 v = row[i];
        ss += v.x * v.x + v.y * v.y + v.z * v.z + v.w * v.w;
    }
    sh[t] = ss;
    __syncthreads();
    for (int s = 128; s > 0; s >>= 1) {
        if (t < s) sh[t] += sh[t + s];
        __syncthreads();
    }
    if (t == 0) g_sumsq_part[b] = sh[0];
    __syncthreads();
    // phase B: column sums over this block's 256 rows
    int f = t & 63, g = t >> 6;
    float cs = 0.f;
    for (int r = 0; r < 64; r++) cs += out[(size_t)(b * 256 + g * 64 + r) * FF + f];
    sh[t] = cs;
    __syncthreads();
    if (t < 64) g_colsum_part[b * FF + t] = sh[t] + sh[t + 64] + sh[t + 128] + sh[t + 192];
}

// ---------------- K5b: final mean(E) + alpha/beta MLPs ------------------------
__global__ void k_final(float* __restrict__ out,
                        const float* __restrict__ wa1, const float* __restrict__ ba1,
                        const float* __restrict__ wa2, const float* __restrict__ ba2,
                        const float* __restrict__ wb1, const float* __restrict__ bb1,
                        const float* __restrict__ wb2, const float* __restrict__ bb2) {
    __shared__ float sh[64];
    int t = threadIdx.x;                 // 64 threads
    float cs = 0.f;
    for (int b = 0; b < 32; b++) cs += g_colsum_part[b * FF + t];
    sh[t] = cs * cs;
    __syncthreads();
    if (t == 0) {
        float s2 = 0.f;
        for (int i = 0; i < 64; i++) s2 += sh[i];
        float sq = 0.f;
        for (int b = 0; b < 32; b++) sq += g_sumsq_part[b];
        // mean(E) = 2*mean_i(sq_i) - (2/N^2) * sum_f colsum_f^2
        float m = 2.0f * sq / (float)NN - 2.0f * s2 / ((float)NN * (float)NN);
        // alpha MLP: 1->2->1, tanh after every linear
        float ha0 = tanhf(m * __ldg(wa1 + 0) + __ldg(ba1 + 0));
        float ha1 = tanhf(m * __ldg(wa1 + 1) + __ldg(ba1 + 1));
        float ao  = tanhf(ha0 * __ldg(wa2 + 0) + ha1 * __ldg(wa2 + 1) + __ldg(ba2));
        // beta MLP
        float hb0 = tanhf(m * __ldg(wb1 + 0) + __ldg(bb1 + 0));
        float hb1 = tanhf(m * __ldg(wb1 + 1) + __ldg(bb1 + 1));
        float bo  = tanhf(hb0 * __ldg(wb2 + 0) + hb1 * __ldg(wb2 + 1) + __ldg(bb2));
        out[NN * FF]     = expf(SLOPEC * ao);
        out[NN * FF + 1] = expf(-SLOPEC * bo);
    }
}

// ---------------- launch ------------------------------------------------------
extern "C" void kernel_launch(void* const* d_in, const int* in_sizes, int n_in,
                              void* d_out, int out_size) {
    const float* x     = (const float*)d_in[0];
    const float* w_in1 = (const float*)d_in[1];
    const float* b_in1 = (const float*)d_in[2];
    const float* w_in2 = (const float*)d_in[3];
    const float* b_in2 = (const float*)d_in[4];
    const float* w_in3 = (const float*)d_in[5];
    const float* b_in3 = (const float*)d_in[6];
    const float* w_a1  = (const float*)d_in[7];
    const float* b_a1  = (const float*)d_in[8];
    const float* w_a2  = (const float*)d_in[9];
    const float* b_a2  = (const float*)d_in[10];
    const float* w_b1  = (const float*)d_in[11];
    const float* b_b1  = (const float*)d_in[12];
    const float* w_b2  = (const float*)d_in[13];
    const float* b_b2  = (const float*)d_in[14];
    float* out = (float*)d_out;

    k_encode<<<NN * FF / 256, 256>>>(x, w_in1, b_in1, w_in2, b_in2, w_in3, b_in3);
    k_gemm_s<<<dim3(64, 64), 256>>>();
    k_colsum<<<dim3(32, 32), 256>>>();
    k_invd<<<32, 256>>>();
    k_av<<<dim3(64, 8), 256>>>();
    k_reduce_out<<<NN * FF / 4 / 256, 256>>>(out);
    k_stats<<<32, 256>>>(out);
    k_final<<<1, 64>>>(out, w_a1, b_a1, w_a2, b_a2, w_b1, b_b1, w_b2, b_b2);
}